// round 7
// baseline (speedup 1.0000x reference)
#include <cuda_runtime.h>
#include <cuda_bf16.h>
#include <cstdint>
#include <math.h>

// ---------------------------------------------------------------------------
// Problem constants
// ---------------------------------------------------------------------------
#define B_   2
#define L_   2521
#define C_   2048
#define H_   16
#define HD_  128
#define M_   (B_ * L_)          // 5042
#define K_   2048
#define KP_  1024               // K/2 u32 pairs per row
#define NQKV 6144

__device__ __constant__ int d_cum[10] = {1, 5, 21, 57, 121, 265, 521, 921, 1497, 2521};

// f32 scratch; q/k stored d-PERMUTED (perm8 within 8-groups) and tf32-rounded,
// v stored plain d-order, tf32-rounded.
__device__ float g_q[B_ * H_ * L_ * HD_];
__device__ float g_k[B_ * H_ * L_ * HD_];
__device__ float g_v[B_ * H_ * L_ * HD_];

// split-bf16 scratch (u32 = packed bf16x2, pair-permuted layout)
__device__ uint32_t g_xh[M_ * KP_],   g_xl[M_ * KP_];
__device__ uint32_t g_wh[NQKV * KP_], g_wl[NQKV * KP_];
__device__ uint32_t g_pwh[C_ * KP_],  g_pwl[C_ * KP_];
__device__ uint32_t g_aoh[M_ * KP_],  g_aol[M_ * KP_];

// ---------------------------------------------------------------------------
// helpers
// ---------------------------------------------------------------------------
__device__ __forceinline__ uint32_t f2tf(float x) {
    uint32_t r;
    asm("cvt.rna.tf32.f32 %0, %1;" : "=r"(r) : "f"(x));
    return r;
}
__device__ __forceinline__ float tf32r(float x) { return __uint_as_float(f2tf(x)); }

__device__ __forceinline__ void mma8(float* c,
                                     uint32_t a0, uint32_t a1, uint32_t a2, uint32_t a3,
                                     uint32_t b0, uint32_t b1)
{
    asm volatile(
        "mma.sync.aligned.m16n8k8.row.col.f32.tf32.tf32.f32 "
        "{%0,%1,%2,%3}, {%4,%5,%6,%7}, {%8,%9}, {%0,%1,%2,%3};"
        : "+f"(c[0]), "+f"(c[1]), "+f"(c[2]), "+f"(c[3])
        : "r"(a0), "r"(a1), "r"(a2), "r"(a3), "r"(b0), "r"(b1));
}

__device__ __forceinline__ void mma16(float* c,
                                      uint32_t a0, uint32_t a1, uint32_t a2, uint32_t a3,
                                      uint32_t b0, uint32_t b1)
{
    asm volatile(
        "mma.sync.aligned.m16n8k16.row.col.f32.bf16.bf16.f32 "
        "{%0,%1,%2,%3}, {%4,%5,%6,%7}, {%8,%9}, {%0,%1,%2,%3};"
        : "+f"(c[0]), "+f"(c[1]), "+f"(c[2]), "+f"(c[3])
        : "r"(a0), "r"(a1), "r"(a2), "r"(a3), "r"(b0), "r"(b1));
}

__device__ __forceinline__ uint32_t smaddr(const void* p) {
    return (uint32_t)__cvta_generic_to_shared(p);
}
__device__ __forceinline__ void cp16(uint32_t dst, const void* src, bool pred) {
    int sz = pred ? 16 : 0;
    asm volatile("cp.async.cg.shared.global [%0], [%1], 16, %2;"
                 :: "r"(dst), "l"(src), "r"(sz));
}
__device__ __forceinline__ void cp_commit() {
    asm volatile("cp.async.commit_group;");
}
template<int N>
__device__ __forceinline__ void cp_wait() {
    asm volatile("cp.async.wait_group %0;" :: "n"(N));
}

// permuted pair column for split-bf16 GEMM fragments
__device__ __forceinline__ int pair_perm(int p) {
    int q = p & 15;
    return (p & ~15) + (q & 8) + (q & 3) * 2 + ((q >> 2) & 1);
}

__device__ __forceinline__ void split_pack(float x0, float x1, uint32_t& hp, uint32_t& lp) {
    __nv_bfloat16 h0 = __float2bfloat16_rn(x0);
    __nv_bfloat16 h1 = __float2bfloat16_rn(x1);
    float l0f = x0 - __bfloat162float(h0);
    float l1f = x1 - __bfloat162float(h1);
    __nv_bfloat16 l0 = __float2bfloat16_rn(l0f);
    __nv_bfloat16 l1 = __float2bfloat16_rn(l1f);
    hp = (uint32_t)__bfloat16_as_ushort(h0) | ((uint32_t)__bfloat16_as_ushort(h1) << 16);
    lp = (uint32_t)__bfloat16_as_ushort(l0) | ((uint32_t)__bfloat16_as_ushort(l1) << 16);
}

// ---------------------------------------------------------------------------
// Kernel 0: f32 -> split-bf16 pre-conversion (permuted layout)
// ---------------------------------------------------------------------------
__global__ void __launch_bounds__(256)
convert_split(const float* __restrict__ src, int which, int npairs)
{
    int i = blockIdx.x * 256 + threadIdx.x;
    if (i >= npairs) return;
    int row = i >> 10;
    int p = i & 1023;
    float2 v = *(const float2*)(src + (size_t)row * K_ + p * 2);
    uint32_t hp, lp;
    split_pack(v.x, v.y, hp, lp);
    int c = pair_perm(p);
    uint32_t* hi = (which == 0) ? g_xh : (which == 1) ? g_wh : g_pwh;
    uint32_t* lo = (which == 0) ? g_xl : (which == 1) ? g_wl : g_pwl;
    hi[(size_t)row * KP_ + c] = hp;
    lo[(size_t)row * KP_ + c] = lp;
}

// ---------------------------------------------------------------------------
// GEMM core: split-bf16, cp.async 3-stage, BK=32 (16 u32/row), XOR swizzle.
// Block tile 128(M) x 256(N), 8 warps = 2m x 4n, warp tile 64x64 (mi=4, j=8).
// physical word = logical ^ ((row & 3) << 2)  -> conflict-free uint2 frags.
// ---------------------------------------------------------------------------
#define GW 16
#define AARR (128 * GW)          // 2048 u32
#define BARR (256 * GW)          // 4096 u32
#define GSTAGE (2 * AARR + 2 * BARR)   // 12288 u32 = 48 KB

__device__ __forceinline__ void gemm_prefetch(
    uint32_t* sbase, const uint32_t* agh, const uint32_t* agl,
    const uint32_t* bgh, const uint32_t* bgl, int ku, bool aok, int tid)
{
    // A: row ra = tid>>1 (0..127), two 16B chunks at fq, fq+4
    int ra = tid >> 1;
    int fq = (tid & 1) * 8;
    int swa = (ra & 3) << 2;
    uint32_t dA = smaddr(sbase + ra * GW);
    cp16(dA + 4 * (fq ^ swa),       agh + ku,     aok);
    cp16(dA + 4 * ((fq + 4) ^ swa), agh + ku + 4, aok);
    uint32_t dAl = dA + AARR * 4;
    cp16(dAl + 4 * (fq ^ swa),       agl + ku,     aok);
    cp16(dAl + 4 * ((fq + 4) ^ swa), agl + ku + 4, aok);
    // B: row rb = tid (0..255), four 16B chunks each for Bh/Bl
    int swb = (tid & 3) << 2;
    uint32_t dB = smaddr(sbase + 2 * AARR + tid * GW);
#pragma unroll
    for (int c2 = 0; c2 < 4; c2++)
        cp16(dB + 4 * ((4 * c2) ^ swb), bgh + ku + 4 * c2, true);
    uint32_t dBl = dB + BARR * 4;
#pragma unroll
    for (int c2 = 0; c2 < 4; c2++)
        cp16(dBl + 4 * ((4 * c2) ^ swb), bgl + ku + 4 * c2, true);
}

__device__ __forceinline__ void gemm_core_bf16s(
    const uint32_t* __restrict__ Ahg, const uint32_t* __restrict__ Alg,
    const uint32_t* __restrict__ Bhg, const uint32_t* __restrict__ Blg,
    int m0, int n0, uint32_t* sm, float acc[4][8][4], int tid)
{
    const int lane = tid & 31, wid = tid >> 5;
    const int g = lane >> 2, t = lane & 3;
    const int mwarp = (wid >> 2) * 64;      // 2 m-warps
    const int nwarp = (wid & 3) * 64;       // 4 n-warps

    const int ra = tid >> 1;
    const int fq = (tid & 1) * 8;
    const bool aok = (m0 + ra) < M_;
    const int arow = aok ? (m0 + ra) : 0;
    const uint32_t* agh = Ahg + (size_t)arow * KP_ + fq;
    const uint32_t* agl = Alg + (size_t)arow * KP_ + fq;
    const uint32_t* bgh = Bhg + (size_t)(n0 + tid) * KP_;
    const uint32_t* bgl = Blg + (size_t)(n0 + tid) * KP_;

    gemm_prefetch(sm,              agh, agl, bgh, bgl, 0,  aok, tid);
    cp_commit();
    gemm_prefetch(sm + GSTAGE,     agh, agl, bgh, bgl, 16, aok, tid);
    cp_commit();

    const int swf = (g & 3) << 2;
    const int NIT = KP_ / 16;    // 64

    for (int it = 0; it < NIT; it++) {
        if (it + 1 >= NIT) cp_wait<0>(); else cp_wait<1>();
        __syncthreads();
        if (it + 2 < NIT) {
            gemm_prefetch(sm + ((it + 2) % 3) * GSTAGE, agh, agl, bgh, bgl,
                          (it + 2) * 16, aok, tid);
            cp_commit();
        }

        uint32_t* S  = sm + (it % 3) * GSTAGE;
        uint32_t* Ah = S;
        uint32_t* Al = S + AARR;
        uint32_t* Bh = S + 2 * AARR;
        uint32_t* Bl = S + 2 * AARR + BARR;

#pragma unroll
        for (int ks = 0; ks < 2; ks++) {
            const int wb = (ks * 8 + 2 * t) ^ swf;
            uint32_t ah[4][4], al[4][4];
#pragma unroll
            for (int mi = 0; mi < 4; mi++) {
                int r0 = mwarp + 16 * mi + g;
                uint2 v0 = *(uint2*)&Ah[r0 * GW + wb];
                uint2 v1 = *(uint2*)&Ah[(r0 + 8) * GW + wb];
                ah[mi][0] = v0.x; ah[mi][2] = v0.y;
                ah[mi][1] = v1.x; ah[mi][3] = v1.y;
                uint2 w0 = *(uint2*)&Al[r0 * GW + wb];
                uint2 w1 = *(uint2*)&Al[(r0 + 8) * GW + wb];
                al[mi][0] = w0.x; al[mi][2] = w0.y;
                al[mi][1] = w1.x; al[mi][3] = w1.y;
            }
#pragma unroll
            for (int j = 0; j < 8; j++) {
                int cn = nwarp + 8 * j + g;
                uint2 bh = *(uint2*)&Bh[cn * GW + wb];
                uint2 bl = *(uint2*)&Bl[cn * GW + wb];
#pragma unroll
                for (int mi = 0; mi < 4; mi++) {
                    mma16(acc[mi][j], ah[mi][0], ah[mi][1], ah[mi][2], ah[mi][3], bh.x, bh.y);
                    mma16(acc[mi][j], ah[mi][0], ah[mi][1], ah[mi][2], ah[mi][3], bl.x, bl.y);
                    mma16(acc[mi][j], al[mi][0], al[mi][1], al[mi][2], al[mi][3], bh.x, bh.y);
                }
            }
        }
    }
}

// ---------------------------------------------------------------------------
// Kernel 1: QKV GEMM + scatter epilogue.
// Block covers 256 output cols = 2 heads within one of q/k/v.
// q/k written with d-permutation perm8 and tf32-rounded; v plain, tf32-rounded.
// ---------------------------------------------------------------------------
__global__ void __launch_bounds__(256, 1)
qkv_gemm(const float* __restrict__ qb, const float* __restrict__ vb)
{
    extern __shared__ uint32_t smu[];
    float acc[4][8][4];
#pragma unroll
    for (int a = 0; a < 4; a++)
#pragma unroll
        for (int b = 0; b < 8; b++)
#pragma unroll
            for (int c = 0; c < 4; c++) acc[a][b][c] = 0.f;

    const int n0 = blockIdx.x * 256;
    const int m0 = blockIdx.y * 128;
    gemm_core_bf16s(g_xh, g_xl, g_wh, g_wl, m0, n0, smu, acc, threadIdx.x);

    const int lane = threadIdx.x & 31, wid = threadIdx.x >> 5;
    const int g = lane >> 2, t = lane & 3;
    const int mwarp = (wid >> 2) * 64, nwarp = (wid & 3) * 64;

    const int tq = n0 >> 11;                 // whole block one of q/k/v
    float* dst = (tq == 0) ? g_q : ((tq == 1) ? g_k : g_v);

    int hh[8], dd[8];
    float2 bias[8];
#pragma unroll
    for (int j = 0; j < 8; j++) {
        int nc = (n0 & 2047) + nwarp + 8 * j + 2 * t;
        hh[j] = nc >> 7;
        dd[j] = nc & 127;
        float b0 = 0.f, b1 = 0.f;
        if (tq == 0) { b0 = qb[nc]; b1 = qb[nc + 1]; }
        else if (tq == 2) { b0 = vb[nc]; b1 = vb[nc + 1]; }
        bias[j] = make_float2(b0, b1);
    }

    const int sl0 = 4 * (t & 1) + (t >> 1);   // perm8(2t); perm8(2t+1) = sl0+2

#pragma unroll
    for (int mi = 0; mi < 4; mi++)
#pragma unroll
        for (int rr = 0; rr < 2; rr++) {
            int gm = m0 + mwarp + 16 * mi + g + 8 * rr;
            if (gm >= M_) continue;
            int b = gm / L_;
            int l = gm - b * L_;
#pragma unroll
            for (int j = 0; j < 8; j++) {
                float ox = acc[mi][j][2 * rr] + bias[j].x;
                float oy = acc[mi][j][2 * rr + 1] + bias[j].y;
                float* p = dst + ((size_t)(b * H_ + hh[j]) * L_ + l) * HD_;
                if (tq == 2) {
                    float2 o = make_float2(tf32r(ox), tf32r(oy));
                    *(float2*)(p + dd[j]) = o;
                } else {
                    int dg = dd[j] - 2 * t;
                    p[dg + sl0]     = ox;
                    p[dg + sl0 + 2] = oy;
                }
            }
        }
}

// ---------------------------------------------------------------------------
// Kernel 2: norm + rope on PERMUTED q/k storage; outputs tf32-rounded.
// ---------------------------------------------------------------------------
__global__ void __launch_bounds__(256)
norm_rope(const float* __restrict__ sml, const float* __restrict__ rope)
{
    const int gw = blockIdx.x * 8 + (threadIdx.x >> 5);
    const int lane = threadIdx.x & 31;
    if (gw >= B_ * H_ * L_) return;
    const int l = gw % L_;
    const int h = (gw / L_) % H_;

    float2 cc = *(const float2*)(rope + (size_t)l * 64 + lane * 2);
    float2 ss = *(const float2*)(rope + (size_t)L_ * 64 + (size_t)l * 64 + lane * 2);
    const float scale = __expf(fminf(sml[h], 4.605170185988091f));
    const size_t base = (size_t)gw * HD_ + (lane >> 1) * 8 + (lane & 1);

    {
        float v0 = g_q[base], v1 = g_q[base + 2], v2 = g_q[base + 4], v3 = g_q[base + 6];
        float ssq = v0 * v0 + v1 * v1 + v2 * v2 + v3 * v3;
#pragma unroll
        for (int o = 16; o; o >>= 1) ssq += __shfl_xor_sync(0xffffffffu, ssq, o);
        float inv = scale / fmaxf(sqrtf(ssq), 1e-12f);
        v0 *= inv; v1 *= inv; v2 *= inv; v3 *= inv;
        g_q[base]     = tf32r(cc.x * v0 - ss.x * v1);
        g_q[base + 2] = tf32r(ss.x * v0 + cc.x * v1);
        g_q[base + 4] = tf32r(cc.y * v2 - ss.y * v3);
        g_q[base + 6] = tf32r(ss.y * v2 + cc.y * v3);
    }
    {
        float v0 = g_k[base], v1 = g_k[base + 2], v2 = g_k[base + 4], v3 = g_k[base + 6];
        float ssq = v0 * v0 + v1 * v1 + v2 * v2 + v3 * v3;
#pragma unroll
        for (int o = 16; o; o >>= 1) ssq += __shfl_xor_sync(0xffffffffu, ssq, o);
        float inv = 1.f / fmaxf(sqrtf(ssq), 1e-12f);
        v0 *= inv; v1 *= inv; v2 *= inv; v3 *= inv;
        g_k[base]     = tf32r(cc.x * v0 - ss.x * v1);
        g_k[base + 2] = tf32r(ss.x * v0 + cc.x * v1);
        g_k[base + 4] = tf32r(cc.y * v2 - ss.y * v3);
        g_k[base + 6] = tf32r(ss.y * v2 + cc.y * v3);
    }
}

// ---------------------------------------------------------------------------
// Kernel 3: flash attention (unchanged from R6).
// ---------------------------------------------------------------------------
#define FW 128
#define FKB (64 * FW)
#define FSTG (2 * FKB)

__device__ __forceinline__ int kend_of(int lq) {
    if (lq >= L_) return 0;
    int ke = 2521;
#pragma unroll
    for (int i = 9; i >= 0; i--)
        if (lq < d_cum[i]) ke = d_cum[i];
    return ke;
}

__device__ __forceinline__ void flash_prefetch(
    float* sm, int s, int k0, const float* kp, const float* vp, int tid)
{
    float* Kb = sm + s * FSTG;
    float* Vb = Kb + FKB;
    int kr = tid >> 2;
    int cb = (tid & 3) * 32;
    bool ok = (k0 + kr) < L_;
    const float* ks = kp + (size_t)(ok ? (k0 + kr) : 0) * HD_ + cb;
    int swk = (kr & 3) << 3;
    uint32_t dK = smaddr(Kb + kr * FW);
#pragma unroll
    for (int i = 0; i < 8; i++)
        cp16(dK + 4 * ((cb + 4 * i) ^ swk), ks + 4 * i, ok);
    int w = kr & 7;
    int slot = (kr & ~7) + (w >> 1) + ((w & 1) << 2);
    int swv = (slot & 3) << 3;
    const float* vs = vp + (size_t)(ok ? (k0 + kr) : 0) * HD_ + cb;
    uint32_t dV = smaddr(Vb + slot * FW);
#pragma unroll
    for (int i = 0; i < 8; i++)
        cp16(dV + 4 * ((cb + 4 * i) ^ swv), vs + 4 * i, ok);
}

__global__ void __launch_bounds__(256, 1)
flash_attn()
{
    extern __shared__ float sm[];

    const int bh = blockIdx.y;
    const int q0 = (gridDim.x - 1 - blockIdx.x) * 128;
    const float* qp = g_q + (size_t)bh * L_ * HD_;
    const float* kp = g_k + (size_t)bh * L_ * HD_;
    const float* vp = g_v + (size_t)bh * L_ * HD_;
    const int tid = threadIdx.x, lane = tid & 31, wid = tid >> 5;
    const int g = lane >> 2, t = lane & 3;
    const int rowbase = wid * 16 + g;
    const int swg = (g & 3) << 3;

    int kmax;
    {
        int lql = min(q0 + 127, L_ - 1);
        kmax = 2521;
#pragma unroll
        for (int i = 9; i >= 0; i--)
            if (lql < d_cum[i]) kmax = d_cum[i];
    }
    const int niter = (kmax + 63) / 64;

    {
        int r = tid >> 1;
        int cb = (tid & 1) * 64;
        bool ok = (q0 + r) < L_;
        const float* src = qp + (size_t)(ok ? (q0 + r) : 0) * HD_ + cb;
        int sw = (r & 3) << 3;
        uint32_t d = smaddr(sm + r * FW);
#pragma unroll
        for (int i = 0; i < 16; i++)
            cp16(d + 4 * ((cb + 4 * i) ^ sw), src + 4 * i, ok);
    }
    cp_commit();
    flash_prefetch(sm, 1, 0, kp, vp, tid);
    cp_commit();
    if (niter > 1) flash_prefetch(sm, 2, 64, kp, vp, tid);
    cp_commit();

    cp_wait<2>();
    __syncthreads();

    uint32_t qf[16][4];
#pragma unroll
    for (int kk8 = 0; kk8 < 16; kk8++) {
        int wb = (kk8 * 8 + 2 * t) ^ swg;
        uint2 a0 = *(const uint2*)&sm[rowbase * FW + wb];
        uint2 a1 = *(const uint2*)&sm[(rowbase + 8) * FW + wb];
        qf[kk8][0] = a0.x; qf[kk8][2] = a0.y;
        qf[kk8][1] = a1.x; qf[kk8][3] = a1.y;
    }
    __syncthreads();

    const int kend0 = kend_of(q0 + rowbase);
    const int kend1 = kend_of(q0 + rowbase + 8);

    float m0v = -1e30f, m1v = -1e30f, l0v = 0.f, l1v = 0.f;
    float O[16][4];
#pragma unroll
    for (int j = 0; j < 16; j++)
#pragma unroll
        for (int c = 0; c < 4; c++) O[j][c] = 0.f;

    for (int it = 0; it < niter; it++) {
        const int k0 = it * 64;
        if (it + 1 >= niter) cp_wait<0>(); else cp_wait<1>();
        __syncthreads();
        if (it + 2 < niter) {
            flash_prefetch(sm, it % 3, (it + 2) * 64, kp, vp, tid);
            cp_commit();
        }

        float* Kb = sm + ((it + 1) % 3) * FSTG;
        float* Vb = Kb + FKB;

        float sc[8][4];
#pragma unroll
        for (int j = 0; j < 8; j++)
#pragma unroll
            for (int c = 0; c < 4; c++) sc[j][c] = 0.f;

#pragma unroll
        for (int kk8 = 0; kk8 < 16; kk8++) {
            int wb = (kk8 * 8 + 2 * t) ^ swg;
#pragma unroll
            for (int j = 0; j < 8; j++) {
                uint2 bb = *(const uint2*)&Kb[(8 * j + g) * FW + wb];
                mma8(sc[j], qf[kk8][0], qf[kk8][1], qf[kk8][2], qf[kk8][3], bb.x, bb.y);
            }
        }

        float rmax0 = -1e30f, rmax1 = -1e30f;
#pragma unroll
        for (int j = 0; j < 8; j++) {
            int c0 = k0 + 8 * j + 2 * t, c1 = c0 + 1;
            if (c0 >= kend0) sc[j][0] = -1e30f;
            if (c1 >= kend0) sc[j][1] = -1e30f;
            if (c0 >= kend1) sc[j][2] = -1e30f;
            if (c1 >= kend1) sc[j][3] = -1e30f;
            rmax0 = fmaxf(rmax0, fmaxf(sc[j][0], sc[j][1]));
            rmax1 = fmaxf(rmax1, fmaxf(sc[j][2], sc[j][3]));
        }
        rmax0 = fmaxf(rmax0, __shfl_xor_sync(0xffffffffu, rmax0, 1));
        rmax0 = fmaxf(rmax0, __shfl_xor_sync(0xffffffffu, rmax0, 2));
        rmax1 = fmaxf(rmax1, __shfl_xor_sync(0xffffffffu, rmax1, 1));
        rmax1 = fmaxf(rmax1, __shfl_xor_sync(0xffffffffu, rmax1, 2));

        float mn0 = fmaxf(m0v, rmax0), mn1 = fmaxf(m1v, rmax1);
        float al0 = __expf(m0v - mn0), al1 = __expf(m1v - mn1);
        float rs0 = 0.f, rs1 = 0.f;
#pragma unroll
        for (int j = 0; j < 8; j++) {
            float p0 = (sc[j][0] > -5e29f) ? __expf(sc[j][0] - mn0) : 0.f;
            float p1 = (sc[j][1] > -5e29f) ? __expf(sc[j][1] - mn0) : 0.f;
            float p2 = (sc[j][2] > -5e29f) ? __expf(sc[j][2] - mn1) : 0.f;
            float p3 = (sc[j][3] > -5e29f) ? __expf(sc[j][3] - mn1) : 0.f;
            rs0 += p0 + p1;
            rs1 += p2 + p3;
            sc[j][0] = p0; sc[j][1] = p1; sc[j][2] = p2; sc[j][3] = p3;
        }
        rs0 += __shfl_xor_sync(0xffffffffu, rs0, 1);
        rs0 += __shfl_xor_sync(0xffffffffu, rs0, 2);
        rs1 += __shfl_xor_sync(0xffffffffu, rs1, 1);
        rs1 += __shfl_xor_sync(0xffffffffu, rs1, 2);
        l0v = l0v * al0 + rs0;
        l1v = l1v * al1 + rs1;
        m0v = mn0; m1v = mn1;

#pragma unroll
        for (int j = 0; j < 16; j++) {
            O[j][0] *= al0; O[j][1] *= al0;
            O[j][2] *= al1; O[j][3] *= al1;
        }

        const int swv = t << 3;
#pragma unroll
        for (int c = 0; c < 8; c++) {
            uint32_t a0 = f2tf(sc[c][0]);
            uint32_t a1 = f2tf(sc[c][2]);
            uint32_t a2 = f2tf(sc[c][1]);
            uint32_t a3 = f2tf(sc[c][3]);
            const float* v0 = Vb + (8 * c + t) * FW;
            const float* v1 = Vb + (8 * c + t + 4) * FW;
#pragma unroll
            for (int j = 0; j < 16; j++) {
                int wv = (g + 8 * j) ^ swv;
                uint32_t b0 = __float_as_uint(v0[wv]);
                uint32_t b1 = __float_as_uint(v1[wv]);
                mma8(O[j], a0, a1, a2, a3, b0, b1);
            }
        }
    }

    const int b = bh >> 4;
    const int h = bh & 15;
#pragma unroll
    for (int rr = 0; rr < 2; rr++) {
        int lq = q0 + rowbase + 8 * rr;
        if (lq >= L_) continue;
        float inv = 1.f / (rr ? l1v : l0v);
        size_t rowoff = (size_t)(b * L_ + lq) * KP_;
#pragma unroll
        for (int j = 0; j < 16; j++) {
            float x0 = O[j][2 * rr] * inv;
            float x1 = O[j][2 * rr + 1] * inv;
            uint32_t hp, lp;
            split_pack(x0, x1, hp, lp);
            int p = h * 64 + 4 * j + t;
            int c = pair_perm(p);
            g_aoh[rowoff + c] = hp;
            g_aol[rowoff + c] = lp;
        }
    }
}

// ---------------------------------------------------------------------------
// Kernel 4: projection GEMM (block 128x256)
// ---------------------------------------------------------------------------
__global__ void __launch_bounds__(256, 1)
proj_gemm(const float* __restrict__ pb, float* __restrict__ out)
{
    extern __shared__ uint32_t smu[];
    float acc[4][8][4];
#pragma unroll
    for (int a = 0; a < 4; a++)
#pragma unroll
        for (int b = 0; b < 8; b++)
#pragma unroll
            for (int c = 0; c < 4; c++) acc[a][b][c] = 0.f;

    const int n0 = blockIdx.x * 256;
    const int m0 = blockIdx.y * 128;
    gemm_core_bf16s(g_aoh, g_aol, g_pwh, g_pwl, m0, n0, smu, acc, threadIdx.x);

    const int lane = threadIdx.x & 31, wid = threadIdx.x >> 5;
    const int g = lane >> 2, t = lane & 3;
    const int mwarp = (wid >> 2) * 64, nwarp = (wid & 3) * 64;

    float2 bias[8];
#pragma unroll
    for (int j = 0; j < 8; j++) {
        int n = n0 + nwarp + 8 * j + 2 * t;
        bias[j] = make_float2(pb[n], pb[n + 1]);
    }

#pragma unroll
    for (int mi = 0; mi < 4; mi++)
#pragma unroll
        for (int rr = 0; rr < 2; rr++) {
            int gm = m0 + mwarp + 16 * mi + g + 8 * rr;
            if (gm >= M_) continue;
            float* p = out + (size_t)gm * C_ + n0 + nwarp;
#pragma unroll
            for (int j = 0; j < 8; j++) {
                float2 o;
                o.x = acc[mi][j][2 * rr] + bias[j].x;
                o.y = acc[mi][j][2 * rr + 1] + bias[j].y;
                *(float2*)(p + 8 * j + 2 * t) = o;
            }
        }
}

// ---------------------------------------------------------------------------
// launch
// ---------------------------------------------------------------------------
extern "C" void kernel_launch(void* const* d_in, const int* in_sizes, int n_in,
                              void* d_out, int out_size)
{
    const float* x    = (const float*)d_in[0];
    const float* Wqkv = (const float*)d_in[1];
    const float* qb   = (const float*)d_in[2];
    const float* vb   = (const float*)d_in[3];
    const float* sml  = (const float*)d_in[4];
    const float* pW   = (const float*)d_in[5];
    const float* pb   = (const float*)d_in[6];
    const float* rope = (const float*)d_in[7];
    float* out = (float*)d_out;

    const size_t gemm_shm  = (size_t)3 * GSTAGE * sizeof(uint32_t);   // 147,456 B
    const size_t flash_shm = (size_t)3 * FSTG * sizeof(float);        // 196,608 B

    cudaFuncSetAttribute(qkv_gemm, cudaFuncAttributeMaxDynamicSharedMemorySize, (int)gemm_shm);
    cudaFuncSetAttribute(proj_gemm, cudaFuncAttributeMaxDynamicSharedMemorySize, (int)gemm_shm);
    cudaFuncSetAttribute(flash_attn, cudaFuncAttributeMaxDynamicSharedMemorySize, (int)flash_shm);

    {
        int np;
        np = M_ * KP_;    convert_split<<<(np + 255) / 256, 256>>>(x, 0, np);
        np = NQKV * KP_;  convert_split<<<(np + 255) / 256, 256>>>(Wqkv, 1, np);
        np = C_ * KP_;    convert_split<<<(np + 255) / 256, 256>>>(pW, 2, np);
    }

    dim3 g1(NQKV / 256, (M_ + 127) / 128);   // 24 x 40
    qkv_gemm<<<g1, 256, gemm_shm>>>(qb, vb);

    int nwarps = B_ * H_ * L_;
    norm_rope<<<(nwarps + 7) / 8, 256>>>(sml, rope);

    dim3 g3((L_ + 127) / 128, B_ * H_);      // 20 x 32
    flash_attn<<<g3, 256, flash_shm>>>();

    dim3 g4(C_ / 256, (M_ + 127) / 128);     // 8 x 40
    proj_gemm<<<g4, 256, gemm_shm>>>(pb, out);
}

// round 8
// speedup vs baseline: 1.2063x; 1.2063x over previous
#include <cuda_runtime.h>
#include <cuda_bf16.h>
#include <cstdint>
#include <math.h>

// ---------------------------------------------------------------------------
// Problem constants
// ---------------------------------------------------------------------------
#define B_   2
#define L_   2521
#define C_   2048
#define H_   16
#define HD_  128
#define M_   (B_ * L_)          // 5042
#define K_   2048
#define KP_  1024               // K/2 u32 pairs per row
#define NQKV 6144

__device__ __constant__ int d_cum[10] = {1, 5, 21, 57, 121, 265, 521, 921, 1497, 2521};

// f32 scratch; q/k stored d-PERMUTED (perm8 within 8-groups) and tf32-rounded,
// v stored plain d-order, tf32-rounded.
__device__ float g_q[B_ * H_ * L_ * HD_];
__device__ float g_k[B_ * H_ * L_ * HD_];
__device__ float g_v[B_ * H_ * L_ * HD_];

// split-bf16 scratch (u32 = packed bf16x2, pair-permuted layout)
__device__ uint32_t g_xh[M_ * KP_],   g_xl[M_ * KP_];
__device__ uint32_t g_wh[NQKV * KP_], g_wl[NQKV * KP_];
__device__ uint32_t g_pwh[C_ * KP_],  g_pwl[C_ * KP_];
__device__ uint32_t g_aoh[M_ * KP_],  g_aol[M_ * KP_];

// ---------------------------------------------------------------------------
// helpers
// ---------------------------------------------------------------------------
__device__ __forceinline__ uint32_t f2tf(float x) {
    uint32_t r;
    asm("cvt.rna.tf32.f32 %0, %1;" : "=r"(r) : "f"(x));
    return r;
}
__device__ __forceinline__ float tf32r(float x) { return __uint_as_float(f2tf(x)); }

__device__ __forceinline__ void mma8(float* c,
                                     uint32_t a0, uint32_t a1, uint32_t a2, uint32_t a3,
                                     uint32_t b0, uint32_t b1)
{
    asm volatile(
        "mma.sync.aligned.m16n8k8.row.col.f32.tf32.tf32.f32 "
        "{%0,%1,%2,%3}, {%4,%5,%6,%7}, {%8,%9}, {%0,%1,%2,%3};"
        : "+f"(c[0]), "+f"(c[1]), "+f"(c[2]), "+f"(c[3])
        : "r"(a0), "r"(a1), "r"(a2), "r"(a3), "r"(b0), "r"(b1));
}

__device__ __forceinline__ void mma16(float* c,
                                      uint32_t a0, uint32_t a1, uint32_t a2, uint32_t a3,
                                      uint32_t b0, uint32_t b1)
{
    asm volatile(
        "mma.sync.aligned.m16n8k16.row.col.f32.bf16.bf16.f32 "
        "{%0,%1,%2,%3}, {%4,%5,%6,%7}, {%8,%9}, {%0,%1,%2,%3};"
        : "+f"(c[0]), "+f"(c[1]), "+f"(c[2]), "+f"(c[3])
        : "r"(a0), "r"(a1), "r"(a2), "r"(a3), "r"(b0), "r"(b1));
}

__device__ __forceinline__ uint32_t smaddr(const void* p) {
    return (uint32_t)__cvta_generic_to_shared(p);
}
__device__ __forceinline__ void cp16(uint32_t dst, const void* src, bool pred) {
    int sz = pred ? 16 : 0;
    asm volatile("cp.async.cg.shared.global [%0], [%1], 16, %2;"
                 :: "r"(dst), "l"(src), "r"(sz));
}
__device__ __forceinline__ void cp_commit() {
    asm volatile("cp.async.commit_group;");
}
template<int N>
__device__ __forceinline__ void cp_wait() {
    asm volatile("cp.async.wait_group %0;" :: "n"(N));
}

// permuted pair column for split-bf16 GEMM fragments
__device__ __forceinline__ int pair_perm(int p) {
    int q = p & 15;
    return (p & ~15) + (q & 8) + (q & 3) * 2 + ((q >> 2) & 1);
}

__device__ __forceinline__ void split_pack(float x0, float x1, uint32_t& hp, uint32_t& lp) {
    __nv_bfloat16 h0 = __float2bfloat16_rn(x0);
    __nv_bfloat16 h1 = __float2bfloat16_rn(x1);
    float l0f = x0 - __bfloat162float(h0);
    float l1f = x1 - __bfloat162float(h1);
    __nv_bfloat16 l0 = __float2bfloat16_rn(l0f);
    __nv_bfloat16 l1 = __float2bfloat16_rn(l1f);
    hp = (uint32_t)__bfloat16_as_ushort(h0) | ((uint32_t)__bfloat16_as_ushort(h1) << 16);
    lp = (uint32_t)__bfloat16_as_ushort(l0) | ((uint32_t)__bfloat16_as_ushort(l1) << 16);
}

// ---------------------------------------------------------------------------
// Kernel 0: f32 -> split-bf16 pre-conversion (permuted layout)
// ---------------------------------------------------------------------------
__global__ void __launch_bounds__(256)
convert_split(const float* __restrict__ src, int which, int npairs)
{
    int i = blockIdx.x * 256 + threadIdx.x;
    if (i >= npairs) return;
    int row = i >> 10;
    int p = i & 1023;
    float2 v = *(const float2*)(src + (size_t)row * K_ + p * 2);
    uint32_t hp, lp;
    split_pack(v.x, v.y, hp, lp);
    int c = pair_perm(p);
    uint32_t* hi = (which == 0) ? g_xh : (which == 1) ? g_wh : g_pwh;
    uint32_t* lo = (which == 0) ? g_xl : (which == 1) ? g_wl : g_pwl;
    hi[(size_t)row * KP_ + c] = hp;
    lo[(size_t)row * KP_ + c] = lp;
}

// ---------------------------------------------------------------------------
// GEMM core (R6 config): split-bf16, cp.async 3-stage, BK=32, XOR swizzle.
// Block 128x128, 8 warps = 4m x 2n, warp tile 32x64. 2 CTAs/SM.
// ---------------------------------------------------------------------------
#define GW 16
#define GARR (128 * GW)          // 2048 u32
#define GSTAGE (4 * GARR)        // 8192 u32 = 32 KB

__device__ __forceinline__ void gemm_prefetch(
    uint32_t* sbase, const uint32_t* agh, const uint32_t* agl,
    const uint32_t* bgh, const uint32_t* bgl, int ku, bool aok, int r, int fq)
{
    int sw = (r & 3) << 2;
    int w0 = ((fq ^ sw)) * 4;
    int w1 = (((fq + 4) ^ sw)) * 4;
    uint32_t dA = smaddr(sbase + r * GW);
    cp16(dA + w0, agh + ku,     aok);
    cp16(dA + w1, agh + ku + 4, aok);
    uint32_t dAl = dA + GARR * 4;
    cp16(dAl + w0, agl + ku,     aok);
    cp16(dAl + w1, agl + ku + 4, aok);
    uint32_t dB = dAl + GARR * 4;
    cp16(dB + w0, bgh + ku,     true);
    cp16(dB + w1, bgh + ku + 4, true);
    uint32_t dBl = dB + GARR * 4;
    cp16(dBl + w0, bgl + ku,     true);
    cp16(dBl + w1, bgl + ku + 4, true);
}

__device__ __forceinline__ void gemm_core_bf16s(
    const uint32_t* __restrict__ Ahg, const uint32_t* __restrict__ Alg,
    const uint32_t* __restrict__ Bhg, const uint32_t* __restrict__ Blg,
    int m0, int n0, uint32_t* sm, float acc[2][8][4], int tid)
{
    const int lane = tid & 31, wid = tid >> 5;
    const int g = lane >> 2, t = lane & 3;
    const int mw = (wid >> 1) * 32, nw = (wid & 1) * 64;

    const int r = tid >> 1;
    const int fq = (tid & 1) * 8;
    const bool aok = (m0 + r) < M_;
    const int arow = aok ? (m0 + r) : 0;
    const uint32_t* agh = Ahg + (size_t)arow * KP_ + fq;
    const uint32_t* agl = Alg + (size_t)arow * KP_ + fq;
    const uint32_t* bgh = Bhg + (size_t)(n0 + r) * KP_ + fq;
    const uint32_t* bgl = Blg + (size_t)(n0 + r) * KP_ + fq;

    gemm_prefetch(sm,              agh, agl, bgh, bgl, 0,  aok, r, fq);
    cp_commit();
    gemm_prefetch(sm + GSTAGE,     agh, agl, bgh, bgl, 16, aok, r, fq);
    cp_commit();

    const int swf = (g & 3) << 2;
    const int NIT = KP_ / 16;    // 64

    for (int it = 0; it < NIT; it++) {
        if (it + 1 >= NIT) cp_wait<0>(); else cp_wait<1>();
        __syncthreads();
        if (it + 2 < NIT) {
            gemm_prefetch(sm + ((it + 2) % 3) * GSTAGE, agh, agl, bgh, bgl,
                          (it + 2) * 16, aok, r, fq);
            cp_commit();
        }

        uint32_t* Ah = sm + (it % 3) * GSTAGE;
        uint32_t* Al = Ah + GARR;
        uint32_t* Bh = Al + GARR;
        uint32_t* Bl = Bh + GARR;

#pragma unroll
        for (int ks = 0; ks < 2; ks++) {
            const int wb = (ks * 8 + 2 * t) ^ swf;
            uint32_t ah[2][4], al[2][4];
#pragma unroll
            for (int mi = 0; mi < 2; mi++) {
                int r0 = mw + 16 * mi + g;
                uint2 v0 = *(uint2*)&Ah[r0 * GW + wb];
                uint2 v1 = *(uint2*)&Ah[(r0 + 8) * GW + wb];
                ah[mi][0] = v0.x; ah[mi][2] = v0.y;
                ah[mi][1] = v1.x; ah[mi][3] = v1.y;
                uint2 w0 = *(uint2*)&Al[r0 * GW + wb];
                uint2 w1 = *(uint2*)&Al[(r0 + 8) * GW + wb];
                al[mi][0] = w0.x; al[mi][2] = w0.y;
                al[mi][1] = w1.x; al[mi][3] = w1.y;
            }
#pragma unroll
            for (int j = 0; j < 8; j++) {
                int cn = nw + 8 * j + g;
                uint2 bh = *(uint2*)&Bh[cn * GW + wb];
                uint2 bl = *(uint2*)&Bl[cn * GW + wb];
#pragma unroll
                for (int mi = 0; mi < 2; mi++) {
                    mma16(acc[mi][j], ah[mi][0], ah[mi][1], ah[mi][2], ah[mi][3], bh.x, bh.y);
                    mma16(acc[mi][j], ah[mi][0], ah[mi][1], ah[mi][2], ah[mi][3], bl.x, bl.y);
                    mma16(acc[mi][j], al[mi][0], al[mi][1], al[mi][2], al[mi][3], bh.x, bh.y);
                }
            }
        }
    }
}

// ---------------------------------------------------------------------------
// Kernel 1: QKV GEMM + scatter epilogue (R6 version).
// ---------------------------------------------------------------------------
__global__ void __launch_bounds__(256, 2)
qkv_gemm(const float* __restrict__ qb, const float* __restrict__ vb)
{
    extern __shared__ uint32_t smu[];
    float acc[2][8][4];
#pragma unroll
    for (int a = 0; a < 2; a++)
#pragma unroll
        for (int b = 0; b < 8; b++)
#pragma unroll
            for (int c = 0; c < 4; c++) acc[a][b][c] = 0.f;

    const int n0 = blockIdx.x * 128;
    const int m0 = blockIdx.y * 128;
    gemm_core_bf16s(g_xh, g_xl, g_wh, g_wl, m0, n0, smu, acc, threadIdx.x);

    const int lane = threadIdx.x & 31, wid = threadIdx.x >> 5;
    const int g = lane >> 2, t = lane & 3;
    const int mw = (wid >> 1) * 32, nw = (wid & 1) * 64;

    const int tq = n0 >> 11;
    const int h = (n0 & 2047) >> 7;
    float* dst = (tq == 0) ? g_q : ((tq == 1) ? g_k : g_v);

    float2 bias[8];
#pragma unroll
    for (int j = 0; j < 8; j++) {
        int d = nw + 8 * j + 2 * t;
        float b0 = 0.f, b1 = 0.f;
        if (tq == 0) { b0 = qb[h * HD_ + d]; b1 = qb[h * HD_ + d + 1]; }
        else if (tq == 2) { b0 = vb[h * HD_ + d]; b1 = vb[h * HD_ + d + 1]; }
        bias[j] = make_float2(b0, b1);
    }

    const int sl0 = 4 * (t & 1) + (t >> 1);   // perm8(2t); perm8(2t+1) = sl0+2

#pragma unroll
    for (int mi = 0; mi < 2; mi++)
#pragma unroll
        for (int rr = 0; rr < 2; rr++) {
            int gm = m0 + mw + 16 * mi + g + 8 * rr;
            if (gm >= M_) continue;
            int b = gm / L_;
            int l = gm - b * L_;
            float* p = dst + ((size_t)(b * H_ + h) * L_ + l) * HD_;
#pragma unroll
            for (int j = 0; j < 8; j++) {
                float ox = acc[mi][j][2 * rr] + bias[j].x;
                float oy = acc[mi][j][2 * rr + 1] + bias[j].y;
                if (tq == 2) {
                    float2 o = make_float2(tf32r(ox), tf32r(oy));
                    *(float2*)(p + nw + 8 * j + 2 * t) = o;
                } else {
                    int dg = nw + 8 * j;
                    p[dg + sl0]     = ox;
                    p[dg + sl0 + 2] = oy;
                }
            }
        }
}

// ---------------------------------------------------------------------------
// Kernel 2: norm + rope on PERMUTED q/k storage; outputs tf32-rounded.
// ---------------------------------------------------------------------------
__global__ void __launch_bounds__(256)
norm_rope(const float* __restrict__ sml, const float* __restrict__ rope)
{
    const int gw = blockIdx.x * 8 + (threadIdx.x >> 5);
    const int lane = threadIdx.x & 31;
    if (gw >= B_ * H_ * L_) return;
    const int l = gw % L_;
    const int h = (gw / L_) % H_;

    float2 cc = *(const float2*)(rope + (size_t)l * 64 + lane * 2);
    float2 ss = *(const float2*)(rope + (size_t)L_ * 64 + (size_t)l * 64 + lane * 2);
    const float scale = __expf(fminf(sml[h], 4.605170185988091f));
    const size_t base = (size_t)gw * HD_ + (lane >> 1) * 8 + (lane & 1);

    {
        float v0 = g_q[base], v1 = g_q[base + 2], v2 = g_q[base + 4], v3 = g_q[base + 6];
        float ssq = v0 * v0 + v1 * v1 + v2 * v2 + v3 * v3;
#pragma unroll
        for (int o = 16; o; o >>= 1) ssq += __shfl_xor_sync(0xffffffffu, ssq, o);
        float inv = scale / fmaxf(sqrtf(ssq), 1e-12f);
        v0 *= inv; v1 *= inv; v2 *= inv; v3 *= inv;
        g_q[base]     = tf32r(cc.x * v0 - ss.x * v1);
        g_q[base + 2] = tf32r(ss.x * v0 + cc.x * v1);
        g_q[base + 4] = tf32r(cc.y * v2 - ss.y * v3);
        g_q[base + 6] = tf32r(ss.y * v2 + cc.y * v3);
    }
    {
        float v0 = g_k[base], v1 = g_k[base + 2], v2 = g_k[base + 4], v3 = g_k[base + 6];
        float ssq = v0 * v0 + v1 * v1 + v2 * v2 + v3 * v3;
#pragma unroll
        for (int o = 16; o; o >>= 1) ssq += __shfl_xor_sync(0xffffffffu, ssq, o);
        float inv = 1.f / fmaxf(sqrtf(ssq), 1e-12f);
        v0 *= inv; v1 *= inv; v2 *= inv; v3 *= inv;
        g_k[base]     = tf32r(cc.x * v0 - ss.x * v1);
        g_k[base + 2] = tf32r(ss.x * v0 + cc.x * v1);
        g_k[base + 4] = tf32r(cc.y * v2 - ss.y * v3);
        g_k[base + 6] = tf32r(ss.y * v2 + cc.y * v3);
    }
}

// ---------------------------------------------------------------------------
// Kernel 3: flash attention — software-pipelined PV (lags S by one k-tile).
// K ring: 3 stages; V ring: 4 stages (PV consumes V[i-1] at iter i).
// P(i-1) held in registers; softmax(i) latency overlapped with PV(i-1) mmas.
// ---------------------------------------------------------------------------
#define FW 128
#define FTILE (64 * FW)           // 8192 floats = 32 KB per tile

__device__ __forceinline__ int kend_of(int lq) {
    if (lq >= L_) return 0;
    int ke = 2521;
#pragma unroll
    for (int i = 9; i >= 0; i--)
        if (lq < d_cum[i]) ke = d_cum[i];
    return ke;
}

__device__ __forceinline__ void flash_prefetch(
    float* sm, int it, int k0, const float* kp, const float* vp, int tid)
{
    float* Kb = sm + (it % 3) * FTILE;
    float* Vb = sm + (3 + (it & 3)) * FTILE;
    int kr = tid >> 2;
    int cb = (tid & 3) * 32;
    bool ok = (k0 + kr) < L_;
    const float* ks = kp + (size_t)(ok ? (k0 + kr) : 0) * HD_ + cb;
    int swk = (kr & 3) << 3;
    uint32_t dK = smaddr(Kb + kr * FW);
#pragma unroll
    for (int i = 0; i < 8; i++)
        cp16(dK + 4 * ((cb + 4 * i) ^ swk), ks + 4 * i, ok);
    // V key-slot permutation: key k -> slot (k>>1) + ((k&1)<<2) within 8-group
    int w = kr & 7;
    int slot = (kr & ~7) + (w >> 1) + ((w & 1) << 2);
    int swv = (slot & 3) << 3;
    const float* vs = vp + (size_t)(ok ? (k0 + kr) : 0) * HD_ + cb;
    uint32_t dV = smaddr(Vb + slot * FW);
#pragma unroll
    for (int i = 0; i < 8; i++)
        cp16(dV + 4 * ((cb + 4 * i) ^ swv), vs + 4 * i, ok);
}

__global__ void __launch_bounds__(256, 1)
flash_attn()
{
    extern __shared__ float sm[];

    const int bh = blockIdx.y;
    const int q0 = (gridDim.x - 1 - blockIdx.x) * 128;
    const float* qp = g_q + (size_t)bh * L_ * HD_;
    const float* kp = g_k + (size_t)bh * L_ * HD_;
    const float* vp = g_v + (size_t)bh * L_ * HD_;
    const int tid = threadIdx.x, lane = tid & 31, wid = tid >> 5;
    const int g = lane >> 2, t = lane & 3;
    const int rowbase = wid * 16 + g;
    const int swg = (g & 3) << 3;

    int kmax;
    {
        int lql = min(q0 + 127, L_ - 1);
        kmax = 2521;
#pragma unroll
        for (int i = 9; i >= 0; i--)
            if (lql < d_cum[i]) kmax = d_cum[i];
    }
    const int niter = (kmax + 63) / 64;

    // stage Q into K-stage-0/1 area (consumed before those stages are filled)
    {
        int r = tid >> 1;
        int cb = (tid & 1) * 64;
        bool ok = (q0 + r) < L_;
        const float* src = qp + (size_t)(ok ? (q0 + r) : 0) * HD_ + cb;
        int sw = (r & 3) << 3;
        uint32_t d = smaddr(sm + r * FW);
#pragma unroll
        for (int i = 0; i < 16; i++)
            cp16(d + 4 * ((cb + 4 * i) ^ sw), src + 4 * i, ok);
    }
    cp_commit();
    cp_wait<0>();
    __syncthreads();

    uint32_t qf[16][4];
#pragma unroll
    for (int kk8 = 0; kk8 < 16; kk8++) {
        int wb = (kk8 * 8 + 2 * t) ^ swg;
        uint2 a0 = *(const uint2*)&sm[rowbase * FW + wb];
        uint2 a1 = *(const uint2*)&sm[(rowbase + 8) * FW + wb];
        qf[kk8][0] = a0.x; qf[kk8][2] = a0.y;
        qf[kk8][1] = a1.x; qf[kk8][3] = a1.y;
    }
    __syncthreads();

    // start K/V pipeline
    flash_prefetch(sm, 0, 0, kp, vp, tid);
    cp_commit();
    if (niter > 1) {
        flash_prefetch(sm, 1, 64, kp, vp, tid);
        cp_commit();
    }

    const int kend0 = kend_of(q0 + rowbase);
    const int kend1 = kend_of(q0 + rowbase + 8);

    float m0v = -1e30f, m1v = -1e30f, l0v = 0.f, l1v = 0.f;
    float al0p = 1.f, al1p = 1.f;           // alpha of previous iter
    uint32_t pprev[8][4];                    // P(i-1) as tf32, PV A-frag order
    float O[16][4];
#pragma unroll
    for (int j = 0; j < 16; j++)
#pragma unroll
        for (int c = 0; c < 4; c++) O[j][c] = 0.f;

    for (int it = 0; it < niter; it++) {
        const int k0 = it * 64;
        if (it + 2 < niter) {
            flash_prefetch(sm, it + 2, (it + 2) * 64, kp, vp, tid);
            cp_commit();
            cp_wait<2>();
        } else if (it + 1 < niter) {
            cp_wait<1>();
        } else {
            cp_wait<0>();
        }
        __syncthreads();

        float* Kb = sm + (it % 3) * FTILE;

        // ---- S = Q K^T for tile it ----
        float sc[8][4];
#pragma unroll
        for (int j = 0; j < 8; j++)
#pragma unroll
            for (int c = 0; c < 4; c++) sc[j][c] = 0.f;

#pragma unroll
        for (int kk8 = 0; kk8 < 16; kk8++) {
            int wb = (kk8 * 8 + 2 * t) ^ swg;
#pragma unroll
            for (int j = 0; j < 8; j++) {
                uint2 bb = *(const uint2*)&Kb[(8 * j + g) * FW + wb];
                mma8(sc[j], qf[kk8][0], qf[kk8][1], qf[kk8][2], qf[kk8][3], bb.x, bb.y);
            }
        }

        // ---- mask + row max (part 1 of softmax) ----
        float rmax0 = -1e30f, rmax1 = -1e30f;
#pragma unroll
        for (int j = 0; j < 8; j++) {
            int c0 = k0 + 8 * j + 2 * t, c1 = c0 + 1;
            if (c0 >= kend0) sc[j][0] = -1e30f;
            if (c1 >= kend0) sc[j][1] = -1e30f;
            if (c0 >= kend1) sc[j][2] = -1e30f;
            if (c1 >= kend1) sc[j][3] = -1e30f;
            rmax0 = fmaxf(rmax0, fmaxf(sc[j][0], sc[j][1]));
            rmax1 = fmaxf(rmax1, fmaxf(sc[j][2], sc[j][3]));
        }
        rmax0 = fmaxf(rmax0, __shfl_xor_sync(0xffffffffu, rmax0, 1));
        rmax0 = fmaxf(rmax0, __shfl_xor_sync(0xffffffffu, rmax0, 2));
        rmax1 = fmaxf(rmax1, __shfl_xor_sync(0xffffffffu, rmax1, 1));
        rmax1 = fmaxf(rmax1, __shfl_xor_sync(0xffffffffu, rmax1, 2));

        // ---- PV for tile it-1 (independent of softmax above; ptxas overlaps) ----
        if (it) {
            float* Vp = sm + (3 + ((it - 1) & 3)) * FTILE;
#pragma unroll
            for (int j = 0; j < 16; j++) {
                O[j][0] *= al0p; O[j][1] *= al0p;
                O[j][2] *= al1p; O[j][3] *= al1p;
            }
            const int swv = t << 3;
#pragma unroll
            for (int c = 0; c < 8; c++) {
                const float* v0 = Vp + (8 * c + t) * FW;
                const float* v1 = Vp + (8 * c + t + 4) * FW;
#pragma unroll
                for (int j = 0; j < 16; j++) {
                    int wv = (g + 8 * j) ^ swv;
                    uint32_t b0 = __float_as_uint(v0[wv]);
                    uint32_t b1 = __float_as_uint(v1[wv]);
                    mma8(O[j], pprev[c][0], pprev[c][1], pprev[c][2], pprev[c][3], b0, b1);
                }
            }
        }

        // ---- softmax part 2: exp, sums, l/m update, save P as pprev ----
        float mn0 = fmaxf(m0v, rmax0), mn1 = fmaxf(m1v, rmax1);
        float al0 = __expf(m0v - mn0), al1 = __expf(m1v - mn1);
        float rs0 = 0.f, rs1 = 0.f;
#pragma unroll
        for (int j = 0; j < 8; j++) {
            float p0 = (sc[j][0] > -5e29f) ? __expf(sc[j][0] - mn0) : 0.f;
            float p1 = (sc[j][1] > -5e29f) ? __expf(sc[j][1] - mn0) : 0.f;
            float p2 = (sc[j][2] > -5e29f) ? __expf(sc[j][2] - mn1) : 0.f;
            float p3 = (sc[j][3] > -5e29f) ? __expf(sc[j][3] - mn1) : 0.f;
            rs0 += p0 + p1;
            rs1 += p2 + p3;
            pprev[j][0] = f2tf(p0);
            pprev[j][1] = f2tf(p2);
            pprev[j][2] = f2tf(p1);
            pprev[j][3] = f2tf(p3);
        }
        rs0 += __shfl_xor_sync(0xffffffffu, rs0, 1);
        rs0 += __shfl_xor_sync(0xffffffffu, rs0, 2);
        rs1 += __shfl_xor_sync(0xffffffffu, rs1, 1);
        rs1 += __shfl_xor_sync(0xffffffffu, rs1, 2);
        l0v = l0v * al0 + rs0;
        l1v = l1v * al1 + rs1;
        m0v = mn0; m1v = mn1;
        al0p = al0; al1p = al1;
    }

    // ---- final PV for tile niter-1 ----
    {
        float* Vp = sm + (3 + ((niter - 1) & 3)) * FTILE;
#pragma unroll
        for (int j = 0; j < 16; j++) {
            O[j][0] *= al0p; O[j][1] *= al0p;
            O[j][2] *= al1p; O[j][3] *= al1p;
        }
        const int swv = t << 3;
#pragma unroll
        for (int c = 0; c < 8; c++) {
            const float* v0 = Vp + (8 * c + t) * FW;
            const float* v1 = Vp + (8 * c + t + 4) * FW;
#pragma unroll
            for (int j = 0; j < 16; j++) {
                int wv = (g + 8 * j) ^ swv;
                uint32_t b0 = __float_as_uint(v0[wv]);
                uint32_t b1 = __float_as_uint(v1[wv]);
                mma8(O[j], pprev[c][0], pprev[c][1], pprev[c][2], pprev[c][3], b0, b1);
            }
        }
    }

    // epilogue: normalize, convert to split-bf16 pairs, write permuted layout
    const int b = bh >> 4;
    const int h = bh & 15;
#pragma unroll
    for (int rr = 0; rr < 2; rr++) {
        int lq = q0 + rowbase + 8 * rr;
        if (lq >= L_) continue;
        float inv = 1.f / (rr ? l1v : l0v);
        size_t rowoff = (size_t)(b * L_ + lq) * KP_;
#pragma unroll
        for (int j = 0; j < 16; j++) {
            float x0 = O[j][2 * rr] * inv;
            float x1 = O[j][2 * rr + 1] * inv;
            uint32_t hp, lp;
            split_pack(x0, x1, hp, lp);
            int p = h * 64 + 4 * j + t;
            int c = pair_perm(p);
            g_aoh[rowoff + c] = hp;
            g_aol[rowoff + c] = lp;
        }
    }
}

// ---------------------------------------------------------------------------
// Kernel 4: projection GEMM (R6 version)
// ---------------------------------------------------------------------------
__global__ void __launch_bounds__(256, 2)
proj_gemm(const float* __restrict__ pb, float* __restrict__ out)
{
    extern __shared__ uint32_t smu[];
    float acc[2][8][4];
#pragma unroll
    for (int a = 0; a < 2; a++)
#pragma unroll
        for (int b = 0; b < 8; b++)
#pragma unroll
            for (int c = 0; c < 4; c++) acc[a][b][c] = 0.f;

    const int n0 = blockIdx.x * 128;
    const int m0 = blockIdx.y * 128;
    gemm_core_bf16s(g_aoh, g_aol, g_pwh, g_pwl, m0, n0, smu, acc, threadIdx.x);

    const int lane = threadIdx.x & 31, wid = threadIdx.x >> 5;
    const int g = lane >> 2, t = lane & 3;
    const int mw = (wid >> 1) * 32, nw = (wid & 1) * 64;

    float2 bias[8];
#pragma unroll
    for (int j = 0; j < 8; j++) {
        int n = n0 + nw + 8 * j + 2 * t;
        bias[j] = make_float2(pb[n], pb[n + 1]);
    }

#pragma unroll
    for (int mi = 0; mi < 2; mi++)
#pragma unroll
        for (int rr = 0; rr < 2; rr++) {
            int gm = m0 + mw + 16 * mi + g + 8 * rr;
            if (gm >= M_) continue;
            float* p = out + (size_t)gm * C_ + n0 + nw;
#pragma unroll
            for (int j = 0; j < 8; j++) {
                float2 o;
                o.x = acc[mi][j][2 * rr] + bias[j].x;
                o.y = acc[mi][j][2 * rr + 1] + bias[j].y;
                *(float2*)(p + 8 * j + 2 * t) = o;
            }
        }
}

// ---------------------------------------------------------------------------
// launch
// ---------------------------------------------------------------------------
extern "C" void kernel_launch(void* const* d_in, const int* in_sizes, int n_in,
                              void* d_out, int out_size)
{
    const float* x    = (const float*)d_in[0];
    const float* Wqkv = (const float*)d_in[1];
    const float* qb   = (const float*)d_in[2];
    const float* vb   = (const float*)d_in[3];
    const float* sml  = (const float*)d_in[4];
    const float* pW   = (const float*)d_in[5];
    const float* pb   = (const float*)d_in[6];
    const float* rope = (const float*)d_in[7];
    float* out = (float*)d_out;

    const size_t gemm_shm  = (size_t)3 * GSTAGE * sizeof(uint32_t);   // 98,304 B
    const size_t flash_shm = (size_t)7 * FTILE * sizeof(float);       // 229,376 B

    cudaFuncSetAttribute(qkv_gemm, cudaFuncAttributeMaxDynamicSharedMemorySize, (int)gemm_shm);
    cudaFuncSetAttribute(proj_gemm, cudaFuncAttributeMaxDynamicSharedMemorySize, (int)gemm_shm);
    cudaFuncSetAttribute(flash_attn, cudaFuncAttributeMaxDynamicSharedMemorySize, (int)flash_shm);

    {
        int np;
        np = M_ * KP_;    convert_split<<<(np + 255) / 256, 256>>>(x, 0, np);
        np = NQKV * KP_;  convert_split<<<(np + 255) / 256, 256>>>(Wqkv, 1, np);
        np = C_ * KP_;    convert_split<<<(np + 255) / 256, 256>>>(pW, 2, np);
    }

    dim3 g1(NQKV / 128, (M_ + 127) / 128);   // 48 x 40
    qkv_gemm<<<g1, 256, gemm_shm>>>(qb, vb);

    int nwarps = B_ * H_ * L_;
    norm_rope<<<(nwarps + 7) / 8, 256>>>(sml, rope);

    dim3 g3((L_ + 127) / 128, B_ * H_);      // 20 x 32
    flash_attn<<<g3, 256, flash_shm>>>();

    dim3 g4(C_ / 128, (M_ + 127) / 128);     // 16 x 40
    proj_gemm<<<g4, 256, gemm_shm>>>(pb, out);
}